// round 16
// baseline (speedup 1.0000x reference)
#include <cuda_runtime.h>
#include <cuda_bf16.h>
#include <cstdint>

#define NN    8192
#define FIN   256
#define FOUT  128
#define SLOPE 0.01f
#define BM    64             // rows per attn CTA
#define BK    64             // j-tile
#define NJ    (NN / BK)      // 128 tiles
#define NCH   8              // j-chunks
#define CHUNK (NJ / NCH)     // 16 tiles per chunk

// ---------------- device scratch ----------------
__device__ uint32_t g_WhF[NN * 64];     // B-fragment-packed Wh (LDS.128 layout)
__device__ float g_src[NN], g_dst[NN];
__device__ float g_A[NN], g_C[NN];      // row factors: exp(s-m), exp(.01s-m)
__device__ float g_E[NN];               // row threshold: exp(-m)
__device__ float g_B[NN], g_D[NN];      // col factors: exp(d), exp(.01d)
__device__ float g_dstmax;
__device__ float g_Opart[NCH][NN * FOUT];
__device__ float g_lpart[NCH][NN];

__device__ __forceinline__ uint32_t pack_bf16x2(float lo, float hi) {
    __nv_bfloat162 h2 = __floats2bfloat162_rn(lo, hi);
    return *reinterpret_cast<uint32_t*>(&h2);
}
__device__ __forceinline__ void mma16816(float* d, uint32_t a0, uint32_t a1,
                                         uint32_t a2, uint32_t a3,
                                         uint32_t b0, uint32_t b1) {
    asm volatile(
        "mma.sync.aligned.m16n8k16.row.col.f32.bf16.bf16.f32 "
        "{%0,%1,%2,%3}, {%4,%5,%6,%7}, {%8,%9}, {%0,%1,%2,%3};"
        : "+f"(d[0]), "+f"(d[1]), "+f"(d[2]), "+f"(d[3])
        : "r"(a0), "r"(a1), "r"(a2), "r"(a3), "r"(b0), "r"(b1));
}
__device__ __forceinline__ void cp16(uint32_t s, const void* g) {
    asm volatile("cp.async.cg.shared.global [%0], [%1], 16;" :: "r"(s), "l"(g));
}
__device__ __forceinline__ void cp4(uint32_t s, const void* g) {
    asm volatile("cp.async.ca.shared.global [%0], [%1], 4;" :: "r"(s), "l"(g));
}
#define CP_COMMIT() asm volatile("cp.async.commit_group;" ::: "memory")
#define CP_WAIT(n)  asm volatile("cp.async.wait_group %0;" :: "n"(n) : "memory")

// smem layout (dynamic):
// whf 2x16384 | adj 2x17408 (stride 68 ints) | vec(B,D) 2x512 | pfrag 8192
#define OFF_WHF  0
#define OFF_ADJ  32768
#define OFF_VEC  (32768 + 2 * 17408)
#define OFF_PF   (OFF_VEC + 2 * 512)
#define SMEM_SZ  (OFF_PF + 8192)        // 76800 B = 75 KB -> 3 CTAs/SM fit

// ---------------------------------------------------------------------------
// Kernel A: Wh = h @ W; emits g_WhF + g_src/g_dst.
// 512 threads, BM=64 (same per-tile cost, 2x warps for latency hiding).
// ---------------------------------------------------------------------------
__global__ __launch_bounds__(512) void wh_kernel(const float* __restrict__ h,
                                                 const float* __restrict__ W,
                                                 const float* __restrict__ a) {
    __shared__ float h_s[64][33];
    __shared__ float W_s[32][FOUT];
    __shared__ float a_s[2 * FOUT];
    __shared__ uint32_t frag_s[4096];

    const int t  = threadIdx.x;
    const int i0 = blockIdx.x * 64;
    if (t < 256) a_s[t] = a[t];

    float C[2][8];
#pragma unroll
    for (int r = 0; r < 2; r++)
#pragma unroll
        for (int c = 0; c < 8; c++) C[r][c] = 0.f;

    const int tr = t >> 4, tc = t & 15;   // rows tr*2+{0,1}, cols tc*8..

    for (int k0 = 0; k0 < FIN; k0 += 32) {
        {   // h tile 64x32: 1 float4 per thread
            int row = t >> 3, colb = (t & 7) * 4;
            float4 v = *reinterpret_cast<const float4*>(
                h + (size_t)(i0 + row) * FIN + k0 + colb);
            h_s[row][colb + 0] = v.x;
            h_s[row][colb + 1] = v.y;
            h_s[row][colb + 2] = v.z;
            h_s[row][colb + 3] = v.w;
        }
        {   // W tile 32x128: 2 float4 per thread
            int row = t >> 4, colb = (t & 15) * 8;
            const float4* s4 =
                reinterpret_cast<const float4*>(W + (size_t)(k0 + row) * FOUT + colb);
            float4* d4 = reinterpret_cast<float4*>(&W_s[row][colb]);
            d4[0] = s4[0];
            d4[1] = s4[1];
        }
        __syncthreads();
#pragma unroll
        for (int kk = 0; kk < 32; kk++) {
            float av0 = h_s[tr * 2 + 0][kk];
            float av1 = h_s[tr * 2 + 1][kk];
            float4 b0 = *reinterpret_cast<const float4*>(&W_s[kk][tc * 8]);
            float4 b1 = *reinterpret_cast<const float4*>(&W_s[kk][tc * 8 + 4]);
            float bv[8] = {b0.x, b0.y, b0.z, b0.w, b1.x, b1.y, b1.z, b1.w};
#pragma unroll
            for (int c = 0; c < 8; c++) {
                C[0][c] += av0 * bv[c];
                C[1][c] += av1 * bv[c];
            }
        }
        __syncthreads();
    }

    float sp[2] = {0.f, 0.f}, dp[2] = {0.f, 0.f};
#pragma unroll
    for (int r = 0; r < 2; r++)
#pragma unroll
        for (int c = 0; c < 8; c++) {
            int col = tc * 8 + c;
            sp[r] += C[r][c] * a_s[col];
            dp[r] += C[r][c] * a_s[FOUT + col];
        }
#pragma unroll
    for (int off = 8; off >= 1; off >>= 1) {
#pragma unroll
        for (int r = 0; r < 2; r++) {
            sp[r] += __shfl_down_sync(0xffffffffu, sp[r], off, 16);
            dp[r] += __shfl_down_sync(0xffffffffu, dp[r], off, 16);
        }
    }
    if (tc == 0) {
#pragma unroll
        for (int r = 0; r < 2; r++) {
            g_src[i0 + tr * 2 + r] = sp[r];
            g_dst[i0 + tr * 2 + r] = dp[r];
        }
    }

    // pack into LDS.128-friendly B-fragment layout (kk = tr*2, even)
    {
        const int wnp = tc >> 3;
        const int nb  = tc & 7;
        const int nbp = nb >> 1, nbl = nb & 1;
        const int kk   = tr * 2;
        const int Kloc = kk >> 4;
        const int klo  = kk & 15;
        const int sel  = klo >> 3;
        const int tig  = (klo >> 1) & 3;
#pragma unroll
        for (int c = 0; c < 8; c++) {
            uint32_t v    = pack_bf16x2(C[0][c], C[1][c]);
            int      lane = c * 4 + tig;
            frag_s[Kloc * 1024 + ((wnp * 4 + nbp) * 32 + lane) * 4 + nbl * 2 + sel] = v;
        }
    }
    __syncthreads();
    {
        uint4*       dst = reinterpret_cast<uint4*>(g_WhF + (size_t)i0 * 64);
        const uint4* src = reinterpret_cast<const uint4*>(frag_s);
        dst[t * 2 + 0] = src[t * 2 + 0];
        dst[t * 2 + 1] = src[t * 2 + 1];
    }
}

// ---------------------------------------------------------------------------
__global__ __launch_bounds__(256) void dstmax_kernel() {
    __shared__ float red[256];
    int t = threadIdx.x;
    float m = -1e30f;
    for (int i = t; i < NN; i += 256) m = fmaxf(m, g_dst[i]);
    red[t] = m;
    __syncthreads();
    for (int s = 128; s > 0; s >>= 1) {
        if (t < s) red[t] = fmaxf(red[t], red[t + s]);
        __syncthreads();
    }
    if (t == 0) g_dstmax = red[0];
}

__global__ __launch_bounds__(256) void vec_kernel() {
    int   i = blockIdx.x * 256 + threadIdx.x;
    float s = g_src[i], d = g_dst[i];
    float x = s + g_dstmax;
    float m = x > 0.f ? x : SLOPE * x;
    g_A[i] = __expf(s - m);
    g_C[i] = __expf(SLOPE * s - m);
    g_E[i] = __expf(-m);
    g_B[i] = __expf(d);
    g_D[i] = __expf(SLOPE * d);
}

// ---------------------------------------------------------------------------
// Kernel D: fused masked softmax numerator, j-split NCH ways.
// grid (128, NCH) x 256 thr (8 warps = 4 wm x 2 wn), 3 CTAs/SM (75 KB smem).
// Branch test via E = exp(-m):  s+d>=0  <=>  A*B >= E  (no dst in loop).
// Double-buffered whf+adj+vec; 2 syncs/tile; whf staged after sync_a (R15).
// ---------------------------------------------------------------------------
__global__ __launch_bounds__(256, 3) void attn_kernel(const int* __restrict__ adj) {
    extern __shared__ __align__(16) char smem[];
    const uint32_t sb = (uint32_t)__cvta_generic_to_shared(smem);

    const int t  = threadIdx.x;
    const int l  = t & 31;
    const int w  = t >> 5;
    const int wm = w & 3;
    const int wn = w >> 2;
    const int i0 = blockIdx.x * BM;
    const int ch = blockIdx.y;

    const int jt0 = ch * CHUNK;
    const int jt1 = jt0 + CHUNK;

    const int r0  = wm * 16 + (l >> 2);
    const int r1  = r0 + 8;
    const int tig = l & 3;

    const float A0 = g_A[i0 + r0], C0 = g_C[i0 + r0], E0 = g_E[i0 + r0];
    const float A1 = g_A[i0 + r1], C1 = g_C[i0 + r1], E1 = g_E[i0 + r1];

    const uint32_t ones_b = (l < 4) ? 0x3F803F80u : 0u;

    float acc[8][4];
#pragma unroll
    for (int nb = 0; nb < 8; nb++)
#pragma unroll
        for (int q = 0; q < 4; q++) acc[nb][q] = 0.f;
    float lacc[4] = {0.f, 0.f, 0.f, 0.f};

    const uint4* wf_g  = reinterpret_cast<const uint4*>(g_WhF);
    const int    arow  = t >> 2;
    const int    aseg  = t & 3;
    const int*   adj_g = adj + (size_t)(i0 + arow) * NN;
    const float* vec_g = (t < 64) ? (g_B + t)
                       : (t < 128) ? (g_D + (t - 64)) : nullptr;

    uint32_t* pf = reinterpret_cast<uint32_t*>(smem + OFF_PF);

    auto stage_A = [&](int b, int jt) {      // adj + B/D vectors
        const int* as = adj_g + jt * BK;
        uint32_t   ad = sb + OFF_ADJ + b * 17408 + arow * 272;
#pragma unroll
        for (int i = 0; i < 4; i++) {
            int ci = aseg + i * 4;
            cp16(ad + ci * 16, as + ci * 4);
        }
        if (t < 128) cp4(sb + OFF_VEC + b * 512 + t * 4, vec_g + jt * BK);
    };
    auto stage_W = [&](int b, int jt) {      // whf B-fragments
        const uint4* ws = wf_g + (size_t)jt * 1024 + t * 4;
        uint32_t     wd = sb + OFF_WHF + b * 16384 + t * 64;
#pragma unroll
        for (int i = 0; i < 4; i++) cp16(wd + i * 16, ws + i);
    };

    // prologue: A+W for tile jt0 as one group
    stage_A(0, jt0);
    stage_W(0, jt0);
    CP_COMMIT();

    for (int jt = jt0; jt < jt1; jt++) {
        const int  buf  = (jt - jt0) & 1;
        const bool more = (jt + 1 < jt1);

        if (more) { stage_A(buf ^ 1, jt + 1); CP_COMMIT(); CP_WAIT(1); }
        else      CP_WAIT(0);
        __syncthreads();    // sync_a: A(jt)+W(jt) visible; all MMA(jt-1) done

        // stage whf(jt+1) now — nobody reads whf[buf^1] anymore
        if (more) { stage_W(buf ^ 1, jt + 1); CP_COMMIT(); }

        // ---- P-phase: own 2 k-steps; STS frags + keep in regs ----
        const float* bfp  = reinterpret_cast<const float*>(smem + OFF_VEC + buf * 512);
        const float* dfp  = bfp + 64;
        const char*  adjb = smem + OFF_ADJ + buf * 17408;
        const int*   ar0s = reinterpret_cast<const int*>(adjb + r0 * 272);
        const int*   ar1s = reinterpret_cast<const int*>(adjb + r1 * 272);

        uint4 aown[2];
#pragma unroll
        for (int q = 0; q < 2; q++) {
            const int s   = wn * 2 + q;
            const int c01 = s * 16 + tig * 2;
            const int c23 = c01 + 8;
            float2 B0 = *reinterpret_cast<const float2*>(bfp + c01);
            float2 B1 = *reinterpret_cast<const float2*>(bfp + c23);
            float2 D0 = *reinterpret_cast<const float2*>(dfp + c01);
            float2 D1 = *reinterpret_cast<const float2*>(dfp + c23);
            int2 m00 = *reinterpret_cast<const int2*>(ar0s + c01);
            int2 m01 = *reinterpret_cast<const int2*>(ar0s + c23);
            int2 m10 = *reinterpret_cast<const int2*>(ar1s + c01);
            int2 m11 = *reinterpret_cast<const int2*>(ar1s + c23);

            // p = adj ? (A*B >= E ? A*B : C*D) : 0
            float pa = A0 * B0.x, qa = C0 * D0.x;
            float pb = A0 * B0.y, qb = C0 * D0.y;
            float pc = A1 * B0.x, qc = C1 * D0.x;
            float pd = A1 * B0.y, qd = C1 * D0.y;
            float pe = A0 * B1.x, qe = C0 * D1.x;
            float pg = A0 * B1.y, qg = C0 * D1.y;
            float ph = A1 * B1.x, qh = C1 * D1.x;
            float pi = A1 * B1.y, qi = C1 * D1.y;
            pa = (pa >= E0) ? pa : qa;  pa = (m00.x > 0) ? pa : 0.f;
            pb = (pb >= E0) ? pb : qb;  pb = (m00.y > 0) ? pb : 0.f;
            pc = (pc >= E1) ? pc : qc;  pc = (m10.x > 0) ? pc : 0.f;
            pd = (pd >= E1) ? pd : qd;  pd = (m10.y > 0) ? pd : 0.f;
            pe = (pe >= E0) ? pe : qe;  pe = (m01.x > 0) ? pe : 0.f;
            pg = (pg >= E0) ? pg : qg;  pg = (m01.y > 0) ? pg : 0.f;
            ph = (ph >= E1) ? ph : qh;  ph = (m11.x > 0) ? ph : 0.f;
            pi = (pi >= E1) ? pi : qi;  pi = (m11.y > 0) ? pi : 0.f;

            aown[q] = make_uint4(pack_bf16x2(pa, pb), pack_bf16x2(pc, pd),
                                 pack_bf16x2(pe, pg), pack_bf16x2(ph, pi));
            *reinterpret_cast<uint4*>(&pf[((wm * 4 + s) * 32 + l) * 4]) = aown[q];
        }
        __syncthreads();    // sync_b: pf visible

        // ---- MMA-phase: all 4 k-steps from whf[buf] + pf (all LDS) ----
        const uint32_t* whf_u =
            reinterpret_cast<const uint32_t*>(smem + OFF_WHF + buf * 16384);
#pragma unroll
        for (int s = 0; s < 4; s++) {
            uint4 af;
            if ((s >> 1) == wn) af = aown[s & 1];
            else af = *reinterpret_cast<const uint4*>(&pf[((wm * 4 + s) * 32 + l) * 4]);

            if (wn == 0)
                mma16816(lacc, af.x, af.y, af.z, af.w, ones_b, ones_b);

#pragma unroll
            for (int nbp = 0; nbp < 4; nbp++) {
                uint4 b = *reinterpret_cast<const uint4*>(
                    &whf_u[s * 1024 + (wn * 4 + nbp) * 128 + l * 4]);
                mma16816(acc[2 * nbp],     af.x, af.y, af.z, af.w, b.x, b.y);
                mma16816(acc[2 * nbp + 1], af.x, af.y, af.z, af.w, b.z, b.w);
            }
        }
        // pf WAR -> next sync_a; whf/adj/vec WAR -> double buffers + staging order
    }

    // ---- write partials ----
    if (wn == 0 && tig == 0) {
        g_lpart[ch][i0 + r0] = lacc[0];
        g_lpart[ch][i0 + r1] = lacc[2];
    }
    float* op = g_Opart[ch];
#pragma unroll
    for (int nb = 0; nb < 8; nb++) {
        int n = wn * 64 + nb * 8 + tig * 2;
        *reinterpret_cast<float2*>(op + (size_t)(i0 + r0) * FOUT + n) =
            make_float2(acc[nb][0], acc[nb][1]);
        *reinterpret_cast<float2*>(op + (size_t)(i0 + r1) * FOUT + n) =
            make_float2(acc[nb][2], acc[nb][3]);
    }
}

// ---------------------------------------------------------------------------
// Kernel E: combine split-j partials: out = sum(O) / sum(l)
// ---------------------------------------------------------------------------
__global__ __launch_bounds__(256) void combine_kernel(float* __restrict__ out) {
    int e = blockIdx.x * 256 + threadIdx.x;
    int i = e >> 5;
    int n = (e & 31) * 4;
    size_t off = (size_t)i * FOUT + n;
    float4 s = make_float4(0.f, 0.f, 0.f, 0.f);
    float  lsum = 0.f;
#pragma unroll
    for (int c = 0; c < NCH; c++) {
        float4 o = *reinterpret_cast<const float4*>(&g_Opart[c][off]);
        s.x += o.x; s.y += o.y; s.z += o.z; s.w += o.w;
        lsum += g_lpart[c][i];
    }
    float inv = 1.f / lsum;
    *reinterpret_cast<float4*>(out + off) =
        make_float4(s.x * inv, s.y * inv, s.z * inv, s.w * inv);
}

// ---------------------------------------------------------------------------
extern "C" void kernel_launch(void* const* d_in, const int* in_sizes, int n_in,
                              void* d_out, int out_size) {
    const float* h   = nullptr;
    const int*   adj = nullptr;
    const float* W   = nullptr;
    const float* a   = nullptr;
    for (int i = 0; i < n_in; i++) {
        switch (in_sizes[i]) {
            case NN * FIN:   h   = (const float*)d_in[i]; break;
            case NN * NN:    adj = (const int*)d_in[i];   break;
            case FIN * FOUT: W   = (const float*)d_in[i]; break;
            case 2 * FOUT:   a   = (const float*)d_in[i]; break;
            default: break;
        }
    }
    float* out = (float*)d_out;

    cudaFuncSetAttribute(attn_kernel, cudaFuncAttributeMaxDynamicSharedMemorySize,
                         SMEM_SZ);

    wh_kernel<<<NN / 64, 512>>>(h, W, a);
    dstmax_kernel<<<1, 256>>>();
    vec_kernel<<<NN / 256, 256>>>();
    attn_kernel<<<dim3(NN / BM, NCH), 256, SMEM_SZ>>>(adj);
    combine_kernel<<<NN * FOUT / 4 / 256, 256>>>(out);
}

// round 17
// speedup vs baseline: 1.1097x; 1.1097x over previous
#include <cuda_runtime.h>
#include <cuda_bf16.h>
#include <cstdint>

#define NN    8192
#define FIN   256
#define FOUT  128
#define SLOPE 0.01f
#define BM    64             // rows per attn CTA
#define BK    64             // j-tile
#define NJ    (NN / BK)      // 128 tiles
#define NCH   8              // j-chunks
#define CHUNK (NJ / NCH)     // 16 tiles per chunk

// ---------------- device scratch ----------------
__device__ uint32_t g_WhF[NN * 64];     // B-fragment-packed Wh (LDS.128 layout)
__device__ float g_src[NN], g_dst[NN];
__device__ float g_A[NN], g_C[NN];      // row factors: exp(s-m), exp(.01s-m)
__device__ float g_E[NN];               // row threshold: exp(-m)
__device__ float g_B[NN], g_D[NN];      // col factors: exp(d), exp(.01d)
__device__ float g_dstmax;
__device__ float g_Opart[NCH][NN * FOUT];
__device__ float g_lpart[NCH][NN];

__device__ __forceinline__ uint32_t pack_bf16x2(float lo, float hi) {
    __nv_bfloat162 h2 = __floats2bfloat162_rn(lo, hi);
    return *reinterpret_cast<uint32_t*>(&h2);
}
__device__ __forceinline__ void mma16816(float* d, uint32_t a0, uint32_t a1,
                                         uint32_t a2, uint32_t a3,
                                         uint32_t b0, uint32_t b1) {
    asm volatile(
        "mma.sync.aligned.m16n8k16.row.col.f32.bf16.bf16.f32 "
        "{%0,%1,%2,%3}, {%4,%5,%6,%7}, {%8,%9}, {%0,%1,%2,%3};"
        : "+f"(d[0]), "+f"(d[1]), "+f"(d[2]), "+f"(d[3])
        : "r"(a0), "r"(a1), "r"(a2), "r"(a3), "r"(b0), "r"(b1));
}
__device__ __forceinline__ void cp16(uint32_t s, const void* g) {
    asm volatile("cp.async.cg.shared.global [%0], [%1], 16;" :: "r"(s), "l"(g));
}
__device__ __forceinline__ void cp4(uint32_t s, const void* g) {
    asm volatile("cp.async.ca.shared.global [%0], [%1], 4;" :: "r"(s), "l"(g));
}
#define CP_COMMIT() asm volatile("cp.async.commit_group;" ::: "memory")
#define CP_WAIT(n)  asm volatile("cp.async.wait_group %0;" :: "n"(n) : "memory")

// smem layout (dynamic):
// whf 2x16384 | adj 2x17408 (stride 68 ints) | vec(B,D) 2x512 | pfrag 8192
#define OFF_WHF  0
#define OFF_ADJ  32768
#define OFF_VEC  (32768 + 2 * 17408)
#define OFF_PF   (OFF_VEC + 2 * 512)
#define SMEM_SZ  (OFF_PF + 8192)        // 76800 B = 75 KB -> 3 CTAs/SM fit

// ---------------------------------------------------------------------------
// Kernel A: Wh = h @ W; emits g_WhF + g_src/g_dst.
// PROVEN R12-R15 shape: 256 thr, BM=64, C[4][8] per thread. Do not shrink.
// ---------------------------------------------------------------------------
__global__ __launch_bounds__(256) void wh_kernel(const float* __restrict__ h,
                                                 const float* __restrict__ W,
                                                 const float* __restrict__ a) {
    __shared__ float h_s[64][33];
    __shared__ float W_s[32][FOUT];
    __shared__ float a_s[2 * FOUT];
    __shared__ uint32_t frag_s[4096];

    const int t  = threadIdx.x;
    const int i0 = blockIdx.x * 64;
    a_s[t] = a[t];

    float C[4][8];
#pragma unroll
    for (int r = 0; r < 4; r++)
#pragma unroll
        for (int c = 0; c < 8; c++) C[r][c] = 0.f;

    const int tr = t >> 4, tc = t & 15;

    for (int k0 = 0; k0 < FIN; k0 += 32) {
        {
            int row = t >> 2, colb = (t & 3) * 8;
            const float4* s4 =
                reinterpret_cast<const float4*>(h + (size_t)(i0 + row) * FIN + k0 + colb);
#pragma unroll
            for (int q = 0; q < 2; q++) {
                float4 v = s4[q];
                h_s[row][colb + 4 * q + 0] = v.x;
                h_s[row][colb + 4 * q + 1] = v.y;
                h_s[row][colb + 4 * q + 2] = v.z;
                h_s[row][colb + 4 * q + 3] = v.w;
            }
        }
        {
            int row = t >> 3, colb = (t & 7) * 16;
            const float4* s4 =
                reinterpret_cast<const float4*>(W + (size_t)(k0 + row) * FOUT + colb);
            float4* d4 = reinterpret_cast<float4*>(&W_s[row][colb]);
#pragma unroll
            for (int q = 0; q < 4; q++) d4[q] = s4[q];
        }
        __syncthreads();
#pragma unroll
        for (int kk = 0; kk < 32; kk++) {
            float av[4];
#pragma unroll
            for (int r = 0; r < 4; r++) av[r] = h_s[tr * 4 + r][kk];
            float4 b0 = *reinterpret_cast<const float4*>(&W_s[kk][tc * 8]);
            float4 b1 = *reinterpret_cast<const float4*>(&W_s[kk][tc * 8 + 4]);
            float bv[8] = {b0.x, b0.y, b0.z, b0.w, b1.x, b1.y, b1.z, b1.w};
#pragma unroll
            for (int r = 0; r < 4; r++)
#pragma unroll
                for (int c = 0; c < 8; c++) C[r][c] += av[r] * bv[c];
        }
        __syncthreads();
    }

    float sp[4], dp[4];
#pragma unroll
    for (int r = 0; r < 4; r++) { sp[r] = 0.f; dp[r] = 0.f; }
#pragma unroll
    for (int r = 0; r < 4; r++)
#pragma unroll
        for (int c = 0; c < 8; c++) {
            int col = tc * 8 + c;
            sp[r] += C[r][c] * a_s[col];
            dp[r] += C[r][c] * a_s[FOUT + col];
        }
#pragma unroll
    for (int off = 8; off >= 1; off >>= 1) {
#pragma unroll
        for (int r = 0; r < 4; r++) {
            sp[r] += __shfl_down_sync(0xffffffffu, sp[r], off, 16);
            dp[r] += __shfl_down_sync(0xffffffffu, dp[r], off, 16);
        }
    }
    if (tc == 0) {
#pragma unroll
        for (int r = 0; r < 4; r++) {
            g_src[i0 + tr * 4 + r] = sp[r];
            g_dst[i0 + tr * 4 + r] = dp[r];
        }
    }

    const int wnp = tc >> 3;
    const int nb  = tc & 7;
    const int nbp = nb >> 1, nbl = nb & 1;
#pragma unroll
    for (int q = 0; q < 2; q++) {
        int kk   = tr * 4 + 2 * q;
        int Kloc = kk >> 4;
        int klo  = kk & 15;
        int sel  = klo >> 3;
        int tig  = (klo >> 1) & 3;
#pragma unroll
        for (int c = 0; c < 8; c++) {
            uint32_t v    = pack_bf16x2(C[2 * q][c], C[2 * q + 1][c]);
            int      lane = c * 4 + tig;
            frag_s[Kloc * 1024 + ((wnp * 4 + nbp) * 32 + lane) * 4 + nbl * 2 + sel] = v;
        }
    }
    __syncthreads();
    {
        uint4*       dst = reinterpret_cast<uint4*>(g_WhF + (size_t)i0 * 64);
        const uint4* src = reinterpret_cast<const uint4*>(frag_s);
#pragma unroll
        for (int i = 0; i < 4; i++) dst[t * 4 + i] = src[t * 4 + i];
    }
}

// ---------------------------------------------------------------------------
__global__ __launch_bounds__(256) void dstmax_kernel() {
    __shared__ float red[256];
    int t = threadIdx.x;
    float m = -1e30f;
    for (int i = t; i < NN; i += 256) m = fmaxf(m, g_dst[i]);
    red[t] = m;
    __syncthreads();
    for (int s = 128; s > 0; s >>= 1) {
        if (t < s) red[t] = fmaxf(red[t], red[t + s]);
        __syncthreads();
    }
    if (t == 0) g_dstmax = red[0];
}

__global__ __launch_bounds__(256) void vec_kernel() {
    int   i = blockIdx.x * 256 + threadIdx.x;
    float s = g_src[i], d = g_dst[i];
    float x = s + g_dstmax;
    float m = x > 0.f ? x : SLOPE * x;
    g_A[i] = __expf(s - m);
    g_C[i] = __expf(SLOPE * s - m);
    g_E[i] = __expf(-m);
    g_B[i] = __expf(d);
    g_D[i] = __expf(SLOPE * d);
}

// ---------------------------------------------------------------------------
// Kernel D: fused masked softmax numerator (R16 proven version).
// grid (128, NCH) x 256 thr (8 warps = 4 wm x 2 wn), 3 CTAs/SM (75 KB smem).
// Branch test via E = exp(-m):  s+d>=0  <=>  A*B >= E  (no dst in loop).
// Double-buffered whf+adj+vec; 2 syncs/tile; whf staged after sync_a.
// ---------------------------------------------------------------------------
__global__ __launch_bounds__(256, 3) void attn_kernel(const int* __restrict__ adj) {
    extern __shared__ __align__(16) char smem[];
    const uint32_t sb = (uint32_t)__cvta_generic_to_shared(smem);

    const int t  = threadIdx.x;
    const int l  = t & 31;
    const int w  = t >> 5;
    const int wm = w & 3;
    const int wn = w >> 2;
    const int i0 = blockIdx.x * BM;
    const int ch = blockIdx.y;

    const int jt0 = ch * CHUNK;
    const int jt1 = jt0 + CHUNK;

    const int r0  = wm * 16 + (l >> 2);
    const int r1  = r0 + 8;
    const int tig = l & 3;

    const float A0 = g_A[i0 + r0], C0 = g_C[i0 + r0], E0 = g_E[i0 + r0];
    const float A1 = g_A[i0 + r1], C1 = g_C[i0 + r1], E1 = g_E[i0 + r1];

    const uint32_t ones_b = (l < 4) ? 0x3F803F80u : 0u;

    float acc[8][4];
#pragma unroll
    for (int nb = 0; nb < 8; nb++)
#pragma unroll
        for (int q = 0; q < 4; q++) acc[nb][q] = 0.f;
    float lacc[4] = {0.f, 0.f, 0.f, 0.f};

    const uint4* wf_g  = reinterpret_cast<const uint4*>(g_WhF);
    const int    arow  = t >> 2;
    const int    aseg  = t & 3;
    const int*   adj_g = adj + (size_t)(i0 + arow) * NN;
    const float* vec_g = (t < 64) ? (g_B + t)
                       : (t < 128) ? (g_D + (t - 64)) : nullptr;

    uint32_t* pf = reinterpret_cast<uint32_t*>(smem + OFF_PF);

    auto stage_A = [&](int b, int jt) {      // adj + B/D vectors
        const int* as = adj_g + jt * BK;
        uint32_t   ad = sb + OFF_ADJ + b * 17408 + arow * 272;
#pragma unroll
        for (int i = 0; i < 4; i++) {
            int ci = aseg + i * 4;
            cp16(ad + ci * 16, as + ci * 4);
        }
        if (t < 128) cp4(sb + OFF_VEC + b * 512 + t * 4, vec_g + jt * BK);
    };
    auto stage_W = [&](int b, int jt) {      // whf B-fragments
        const uint4* ws = wf_g + (size_t)jt * 1024 + t * 4;
        uint32_t     wd = sb + OFF_WHF + b * 16384 + t * 64;
#pragma unroll
        for (int i = 0; i < 4; i++) cp16(wd + i * 16, ws + i);
    };

    // prologue: A+W for tile jt0 as one group
    stage_A(0, jt0);
    stage_W(0, jt0);
    CP_COMMIT();

    for (int jt = jt0; jt < jt1; jt++) {
        const int  buf  = (jt - jt0) & 1;
        const bool more = (jt + 1 < jt1);

        if (more) { stage_A(buf ^ 1, jt + 1); CP_COMMIT(); CP_WAIT(1); }
        else      CP_WAIT(0);
        __syncthreads();    // sync_a: A(jt)+W(jt) visible; all MMA(jt-1) done

        // stage whf(jt+1) now — nobody reads whf[buf^1] anymore
        if (more) { stage_W(buf ^ 1, jt + 1); CP_COMMIT(); }

        // ---- P-phase: own 2 k-steps; STS frags + keep in regs ----
        const float* bfp  = reinterpret_cast<const float*>(smem + OFF_VEC + buf * 512);
        const float* dfp  = bfp + 64;
        const char*  adjb = smem + OFF_ADJ + buf * 17408;
        const int*   ar0s = reinterpret_cast<const int*>(adjb + r0 * 272);
        const int*   ar1s = reinterpret_cast<const int*>(adjb + r1 * 272);

        uint4 aown[2];
#pragma unroll
        for (int q = 0; q < 2; q++) {
            const int s   = wn * 2 + q;
            const int c01 = s * 16 + tig * 2;
            const int c23 = c01 + 8;
            float2 B0 = *reinterpret_cast<const float2*>(bfp + c01);
            float2 B1 = *reinterpret_cast<const float2*>(bfp + c23);
            float2 D0 = *reinterpret_cast<const float2*>(dfp + c01);
            float2 D1 = *reinterpret_cast<const float2*>(dfp + c23);
            int2 m00 = *reinterpret_cast<const int2*>(ar0s + c01);
            int2 m01 = *reinterpret_cast<const int2*>(ar0s + c23);
            int2 m10 = *reinterpret_cast<const int2*>(ar1s + c01);
            int2 m11 = *reinterpret_cast<const int2*>(ar1s + c23);

            // p = adj ? (A*B >= E ? A*B : C*D) : 0
            float pa = A0 * B0.x, qa = C0 * D0.x;
            float pb = A0 * B0.y, qb = C0 * D0.y;
            float pc = A1 * B0.x, qc = C1 * D0.x;
            float pd = A1 * B0.y, qd = C1 * D0.y;
            float pe = A0 * B1.x, qe = C0 * D1.x;
            float pg = A0 * B1.y, qg = C0 * D1.y;
            float ph = A1 * B1.x, qh = C1 * D1.x;
            float pi = A1 * B1.y, qi = C1 * D1.y;
            pa = (pa >= E0) ? pa : qa;  pa = (m00.x > 0) ? pa : 0.f;
            pb = (pb >= E0) ? pb : qb;  pb = (m00.y > 0) ? pb : 0.f;
            pc = (pc >= E1) ? pc : qc;  pc = (m10.x > 0) ? pc : 0.f;
            pd = (pd >= E1) ? pd : qd;  pd = (m10.y > 0) ? pd : 0.f;
            pe = (pe >= E0) ? pe : qe;  pe = (m01.x > 0) ? pe : 0.f;
            pg = (pg >= E0) ? pg : qg;  pg = (m01.y > 0) ? pg : 0.f;
            ph = (ph >= E1) ? ph : qh;  ph = (m11.x > 0) ? ph : 0.f;
            pi = (pi >= E1) ? pi : qi;  pi = (m11.y > 0) ? pi : 0.f;

            aown[q] = make_uint4(pack_bf16x2(pa, pb), pack_bf16x2(pc, pd),
                                 pack_bf16x2(pe, pg), pack_bf16x2(ph, pi));
            *reinterpret_cast<uint4*>(&pf[((wm * 4 + s) * 32 + l) * 4]) = aown[q];
        }
        __syncthreads();    // sync_b: pf visible

        // ---- MMA-phase: all 4 k-steps from whf[buf] + pf (all LDS) ----
        const uint32_t* whf_u =
            reinterpret_cast<const uint32_t*>(smem + OFF_WHF + buf * 16384);
#pragma unroll
        for (int s = 0; s < 4; s++) {
            uint4 af;
            if ((s >> 1) == wn) af = aown[s & 1];
            else af = *reinterpret_cast<const uint4*>(&pf[((wm * 4 + s) * 32 + l) * 4]);

            if (wn == 0)
                mma16816(lacc, af.x, af.y, af.z, af.w, ones_b, ones_b);

#pragma unroll
            for (int nbp = 0; nbp < 4; nbp++) {
                uint4 b = *reinterpret_cast<const uint4*>(
                    &whf_u[s * 1024 + (wn * 4 + nbp) * 128 + l * 4]);
                mma16816(acc[2 * nbp],     af.x, af.y, af.z, af.w, b.x, b.y);
                mma16816(acc[2 * nbp + 1], af.x, af.y, af.z, af.w, b.z, b.w);
            }
        }
        // pf WAR -> next sync_a; whf/adj/vec WAR -> double buffers + staging order
    }

    // ---- write partials ----
    if (wn == 0 && tig == 0) {
        g_lpart[ch][i0 + r0] = lacc[0];
        g_lpart[ch][i0 + r1] = lacc[2];
    }
    float* op = g_Opart[ch];
#pragma unroll
    for (int nb = 0; nb < 8; nb++) {
        int n = wn * 64 + nb * 8 + tig * 2;
        *reinterpret_cast<float2*>(op + (size_t)(i0 + r0) * FOUT + n) =
            make_float2(acc[nb][0], acc[nb][1]);
        *reinterpret_cast<float2*>(op + (size_t)(i0 + r1) * FOUT + n) =
            make_float2(acc[nb][2], acc[nb][3]);
    }
}

// ---------------------------------------------------------------------------
// Kernel E: combine split-j partials: out = sum(O) / sum(l)
// ---------------------------------------------------------------------------
__global__ __launch_bounds__(256) void combine_kernel(float* __restrict__ out) {
    int e = blockIdx.x * 256 + threadIdx.x;
    int i = e >> 5;
    int n = (e & 31) * 4;
    size_t off = (size_t)i * FOUT + n;
    float4 s = make_float4(0.f, 0.f, 0.f, 0.f);
    float  lsum = 0.f;
#pragma unroll
    for (int c = 0; c < NCH; c++) {
        float4 o = *reinterpret_cast<const float4*>(&g_Opart[c][off]);
        s.x += o.x; s.y += o.y; s.z += o.z; s.w += o.w;
        lsum += g_lpart[c][i];
    }
    float inv = 1.f / lsum;
    *reinterpret_cast<float4*>(out + off) =
        make_float4(s.x * inv, s.y * inv, s.z * inv, s.w * inv);
}

// ---------------------------------------------------------------------------
extern "C" void kernel_launch(void* const* d_in, const int* in_sizes, int n_in,
                              void* d_out, int out_size) {
    const float* h   = nullptr;
    const int*   adj = nullptr;
    const float* W   = nullptr;
    const float* a   = nullptr;
    for (int i = 0; i < n_in; i++) {
        switch (in_sizes[i]) {
            case NN * FIN:   h   = (const float*)d_in[i]; break;
            case NN * NN:    adj = (const int*)d_in[i];   break;
            case FIN * FOUT: W   = (const float*)d_in[i]; break;
            case 2 * FOUT:   a   = (const float*)d_in[i]; break;
            default: break;
        }
    }
    float* out = (float*)d_out;

    cudaFuncSetAttribute(attn_kernel, cudaFuncAttributeMaxDynamicSharedMemorySize,
                         SMEM_SZ);

    wh_kernel<<<NN / 64, 256>>>(h, W, a);
    dstmax_kernel<<<1, 256>>>();
    vec_kernel<<<NN / 256, 256>>>();
    attn_kernel<<<dim3(NN / BM, NCH), 256, SMEM_SZ>>>(adj);
    combine_kernel<<<NN * FOUT / 4 / 256, 256>>>(out);
}